// round 16
// baseline (speedup 1.0000x reference)
#include <cuda_runtime.h>
#include <cuda_fp16.h>
#include <cstdint>
#include <math.h>

#define BATCH 4
#define TSEQ  4096
#define EMB   100
#define HS    64
#define NQT   32            // 128-row q tiles per batch
#define MAXCH 8
#define ITEMS_PER_B 144     // sum over qt of ceil((qt+1)/4)

// ---------------- global scratch ----------------
__device__ __align__(16) __half g_q[BATCH * TSEQ * HS];          // q * log2e/8, fp16
__device__ __align__(16) __half g_k[BATCH * TSEQ * HS];          // fp16
__device__ __align__(16) __half g_vt[BATCH * 64 * HS * 64];      // [ktile][dim][tok]
__device__ __align__(16) float g_wp[3 * 50 * HS * 2];            // W pairs: [m][e/2][j][2]
__device__ __align__(16) __half g_part[BATCH * NQT * MAXCH * 128 * HS]; // O partials fp16
__device__ float g_l[BATCH * NQT * MAXCH * 128];                 // row sums fp32
__device__ int   g_cnt[BATCH * NQT];                             // split-K fixup counters
                                                                 // (zero-init; self-reset)

// ---------------- PTX helpers ---------------
__device__ __forceinline__ uint32_t smem_u32(const void* p) {
    uint32_t a;
    asm("{ .reg .u64 t; cvta.to.shared.u64 t, %1; cvt.u32.u64 %0, t; }" : "=r"(a) : "l"(p));
    return a;
}
__device__ __forceinline__ uint32_t h2ex2(uint32_t x) {
    uint32_t r; asm("ex2.approx.f16x2 %0, %1;" : "=r"(r) : "r"(x)); return r;
}
__device__ __forceinline__ void ffma2(unsigned long long& d,
                                      unsigned long long a, unsigned long long b) {
    asm("fma.rn.f32x2 %0, %1, %2, %0;" : "+l"(d) : "l"(a), "l"(b));
}
__device__ __forceinline__ void cpa16(uint32_t dst, const void* src) {
    asm volatile("cp.async.cg.shared.global [%0], [%1], 16;" :: "r"(dst), "l"(src));
}
__device__ __forceinline__ void cpa_commit() { asm volatile("cp.async.commit_group;" ::: "memory"); }
__device__ __forceinline__ void cpa_wait1()  { asm volatile("cp.async.wait_group 1;" ::: "memory"); }
__device__ __forceinline__ void ldsm4(uint32_t* r, uint32_t addr) {
    asm volatile("ldmatrix.sync.aligned.m8n8.x4.shared.b16 {%0,%1,%2,%3}, [%4];"
        : "=r"(r[0]), "=r"(r[1]), "=r"(r[2]), "=r"(r[3]) : "r"(addr));
}
__device__ __forceinline__ void mma16816(float* c, const uint32_t* a, uint32_t b0, uint32_t b1) {
    asm volatile("mma.sync.aligned.m16n8k16.row.col.f32.f16.f16.f32 "
        "{%0,%1,%2,%3}, {%4,%5,%6,%7}, {%8,%9}, {%0,%1,%2,%3};"
        : "+f"(c[0]), "+f"(c[1]), "+f"(c[2]), "+f"(c[3])
        : "r"(a[0]), "r"(a[1]), "r"(a[2]), "r"(a[3]), "r"(b0), "r"(b1));
}

// attn SMEM: K and V tile PAIRS, double buffered (16KB per pair per part)
#define OFF_K 0
#define OFF_V 32768
#define SMEM_TOTAL 65536

// proj SMEM
#define XS_PAD 102
#define PROJ_XS_FLOATS (128 * XS_PAD)
#define PROJ_WS_FLOATS (3 * 50 * HS * 2)
#define PROJ_SMEM ((PROJ_XS_FLOATS + PROJ_WS_FLOATS) * 4)

// ---------------------------------------------------------------------------
// Kernel 0: repack W -> g_wp[m][e/2][j][2]
// ---------------------------------------------------------------------------
__global__ void wp_kernel(const float* __restrict__ Wq,
                          const float* __restrict__ Wk,
                          const float* __restrict__ Wv)
{
    for (int i = blockIdx.x * 256 + threadIdx.x; i < 3 * 50 * HS; i += gridDim.x * 256) {
        const int m = i / (50 * HS);
        const int r = i % (50 * HS);
        const int ep = r / HS, j = r % HS;
        const float* W = (m == 0) ? Wq : ((m == 1) ? Wk : Wv);
        g_wp[i * 2 + 0] = W[(2 * ep)     * HS + j];
        g_wp[i * 2 + 1] = W[(2 * ep + 1) * HS + j];
    }
}

// ---------------------------------------------------------------------------
// Kernel 1: fused Q/K/V projection, SMEM-tiled, packed f32x2 FMA, m-fused.
// ---------------------------------------------------------------------------
__global__ __launch_bounds__(256) void proj_kernel(const float* __restrict__ x)
{
    extern __shared__ float psm[];
    float* xs = psm;                        // [128][XS_PAD]
    float* ws = psm + PROJ_XS_FLOATS;       // [3][50][64][2]

    const int tid = threadIdx.x;
    const int row0g = blockIdx.x * 128;

    const float* xg = x + (size_t)row0g * EMB;
    for (int i = tid; i < 128 * EMB; i += 256)
        xs[(i / EMB) * XS_PAD + (i % EMB)] = xg[i];
    for (int i = tid; i < PROJ_WS_FLOATS / 4; i += 256)
        *(float4*)(ws + i * 4) = *(const float4*)(g_wp + i * 4);
    __syncthreads();

    const int rt = tid >> 4;
    const int ct = tid & 15;
    const int row0 = rt * 8;
    const int j0 = ct * 4;

    unsigned long long acc[3][32];
#pragma unroll
    for (int m = 0; m < 3; m++)
#pragma unroll
        for (int q = 0; q < 32; q++) acc[m][q] = 0ull;

    const float* wsb = ws + j0 * 2;
#pragma unroll 1
    for (int ep = 0; ep < 50; ep++) {
        unsigned long long xv[8];
#pragma unroll
        for (int r = 0; r < 8; r++)
            xv[r] = *(const unsigned long long*)(&xs[(row0 + r) * XS_PAD + 2 * ep]);
#pragma unroll
        for (int m = 0; m < 3; m++) {
            const float* wsm = wsb + m * (50 * HS * 2) + ep * (HS * 2);
            const ulonglong2 wa = *(const ulonglong2*)(wsm);
            const ulonglong2 wb = *(const ulonglong2*)(wsm + 4);
#pragma unroll
            for (int r = 0; r < 8; r++) {
                ffma2(acc[m][r * 4 + 0], xv[r], wa.x);
                ffma2(acc[m][r * 4 + 1], xv[r], wa.y);
                ffma2(acc[m][r * 4 + 2], xv[r], wb.x);
                ffma2(acc[m][r * 4 + 3], xv[r], wb.y);
            }
        }
    }

    const float QSCALE = 0.125f * 1.4426950408889634f;

#pragma unroll
    for (int r = 0; r < 8; r++) {
        float v0 = ((float2*)&acc[0][r*4+0])->x + ((float2*)&acc[0][r*4+0])->y;
        float v1 = ((float2*)&acc[0][r*4+1])->x + ((float2*)&acc[0][r*4+1])->y;
        float v2 = ((float2*)&acc[0][r*4+2])->x + ((float2*)&acc[0][r*4+2])->y;
        float v3 = ((float2*)&acc[0][r*4+3])->x + ((float2*)&acc[0][r*4+3])->y;
        __half2 h01 = __floats2half2_rn(v0 * QSCALE, v1 * QSCALE);
        __half2 h23 = __floats2half2_rn(v2 * QSCALE, v3 * QSCALE);
        uint2 u = make_uint2(*(uint32_t*)&h01, *(uint32_t*)&h23);
        *(uint2*)(&g_q[(size_t)(row0g + row0 + r) * HS + j0]) = u;
    }
#pragma unroll
    for (int r = 0; r < 8; r++) {
        float v0 = ((float2*)&acc[1][r*4+0])->x + ((float2*)&acc[1][r*4+0])->y;
        float v1 = ((float2*)&acc[1][r*4+1])->x + ((float2*)&acc[1][r*4+1])->y;
        float v2 = ((float2*)&acc[1][r*4+2])->x + ((float2*)&acc[1][r*4+2])->y;
        float v3 = ((float2*)&acc[1][r*4+3])->x + ((float2*)&acc[1][r*4+3])->y;
        __half2 h01 = __floats2half2_rn(v0, v1);
        __half2 h23 = __floats2half2_rn(v2, v3);
        uint2 u = make_uint2(*(uint32_t*)&h01, *(uint32_t*)&h23);
        *(uint2*)(&g_k[(size_t)(row0g + row0 + r) * HS + j0]) = u;
    }
    {
        const int grow0 = row0g + row0;
        const int kt = grow0 >> 6;
        const int tok0 = grow0 & 63;
#pragma unroll
        for (int jj = 0; jj < 4; jj++) {
            union { __half h[8]; uint4 u; } vt;
#pragma unroll
            for (int r = 0; r < 8; r++) {
                const float2 f = *(float2*)&acc[2][r * 4 + jj];
                vt.h[r] = __float2half_rn(f.x + f.y);
            }
            *(uint4*)(&g_vt[(size_t)kt * (HS * 64) + (j0 + jj) * 64 + tok0]) = vt.u;
        }
    }
}

// ---------------------------------------------------------------------------
// Kernel 2: mma.sync fp16 split-K causal flash attention + fused fixup.
// Last-arriving chunk CTA per (b,qt) merges partials and writes output.
// ---------------------------------------------------------------------------
__device__ __forceinline__ void issue_pair(uint32_t sb, int tid, int buf,
                                           int b, int ktile)
{
    const char* kp = (const char*)g_k + (size_t)(b * TSEQ + ktile * 64) * HS * 2;
    const char* vp = (const char*)g_vt + (size_t)(b * 64 + ktile) * (HS * 64) * 2;
#pragma unroll
    for (int rep = 0; rep < 4; rep++) {
        const int idx = tid + rep * 256;
        const int row = idx >> 3, c = idx & 7;
        const int dsw = row * 128 + ((c ^ (row & 7)) * 16);
        const int ssw = row * 128 + c * 16;
        cpa16(sb + OFF_K + buf * 16384 + dsw, kp + ssw);
        cpa16(sb + OFF_V + buf * 16384 + dsw, vp + ssw);
    }
}

__global__ __launch_bounds__(256, 2) void attn_kernel(float* __restrict__ out)
{
    extern __shared__ char sm[];
    const uint32_t sb = smem_u32(sm);
    __shared__ int s_last;
    const int tid  = threadIdx.x;
    const int w    = tid >> 5;
    const int lane = tid & 31;
    const int gid  = lane >> 2;
    const int tig  = lane & 3;
    const unsigned FULL = 0xffffffffu;

    const int b = blockIdx.x & 3;
    const int i = 143 - (int)(blockIdx.x >> 2);
    int g = 1;
    while (i >= 2 * g * (g + 1)) g++;
    const int off = i - 2 * g * (g - 1);
    const int qt = 4 * (g - 1) + off / g;
    const int ch = off % g;
    const int k0t = ch * 8;
    const int n = min(k0t + 8, 2 * qt + 2) - k0t;
    const int np = n >> 1;
    const int nch = qt / 4 + 1;     // chunks for this qt

    uint32_t qf[4][4];
    {
        const __half* qb = g_q + (size_t)(b * TSEQ + qt * 128 + w * 16) * HS;
#pragma unroll
        for (int kk = 0; kk < 4; kk++) {
            const int cA = kk * 16 + tig * 2;
            qf[kk][0] = *(const uint32_t*)(qb + gid * HS + cA);
            qf[kk][1] = *(const uint32_t*)(qb + (gid + 8) * HS + cA);
            qf[kk][2] = *(const uint32_t*)(qb + gid * HS + cA + 8);
            qf[kk][3] = *(const uint32_t*)(qb + (gid + 8) * HS + cA + 8);
        }
    }

    float oacc[8][4];
#pragma unroll
    for (int j = 0; j < 8; j++)
#pragma unroll
        for (int q = 0; q < 4; q++) oacc[j][q] = 0.f;
    float lsumA = 0.f, lsumB = 0.f;
    const int growA = qt * 128 + w * 16 + gid;
    const int growB = growA + 8;
    const int wrow0 = qt * 128 + w * 16;

    const int lgrp = lane >> 3, li = lane & 7;
    const int rsel = (lgrp >> 1) * 8 + li;
    const int csel = lgrp & 1;

    issue_pair(sb, tid, 0, b, k0t);
    cpa_commit();

    for (int pt = 0; pt < np; pt++) {
        const int buf = pt & 1;
        if (pt + 1 < np) issue_pair(sb, tid, buf ^ 1, b, k0t + 2 * (pt + 1));
        cpa_commit();
        cpa_wait1();
        __syncthreads();

#pragma unroll
        for (int sub = 0; sub < 2; sub++) {
            const int tglob = k0t + 2 * pt + sub;
            const uint32_t kbase = sb + OFF_K + buf * 16384 + sub * 8192;
            const uint32_t vbase = sb + OFF_V + buf * 16384 + sub * 8192;

            float sacc[8][4];
#pragma unroll
            for (int j = 0; j < 8; j++)
#pragma unroll
                for (int q = 0; q < 4; q++) sacc[j][q] = 0.f;

#pragma unroll
            for (int kk = 0; kk < 4; kk++) {
                const int c = kk * 2 + csel;
                uint32_t bh[4][4];
#pragma unroll
                for (int jp = 0; jp < 4; jp++) {
                    const int tok = jp * 16 + rsel;
                    ldsm4(bh[jp], kbase + tok * 128 + ((c ^ (tok & 7)) * 16));
                }
#pragma unroll
                for (int jp = 0; jp < 4; jp++) {
                    mma16816(sacc[2 * jp],     qf[kk], bh[jp][0], bh[jp][1]);
                    mma16816(sacc[2 * jp + 1], qf[kk], bh[jp][2], bh[jp][3]);
                }
            }

            uint32_t pf[4][4];
            __half2 lA2 = __floats2half2_rn(0.f, 0.f);
            __half2 lB2 = lA2;
            const bool full = (tglob * 64 + 63) <= wrow0;
            if (full) {
#pragma unroll
                for (int j = 0; j < 8; j++) {
                    __half2 hA = __floats2half2_rn(sacc[j][0], sacc[j][1]);
                    __half2 hB = __floats2half2_rn(sacc[j][2], sacc[j][3]);
                    uint32_t pa = h2ex2(*(uint32_t*)&hA);
                    uint32_t pb = h2ex2(*(uint32_t*)&hB);
                    lA2 = __hadd2(lA2, *(__half2*)&pa);
                    lB2 = __hadd2(lB2, *(__half2*)&pb);
                    const int kt = j >> 1, hi = (j & 1) * 2;
                    pf[kt][hi]     = pa;
                    pf[kt][hi + 1] = pb;
                }
            } else {
#pragma unroll
                for (int j = 0; j < 8; j++) {
                    const int tok0 = tglob * 64 + j * 8 + tig * 2;
                    const uint32_t mA = (tok0 + 1 <= growA) ? 0xFFFFFFFFu
                                       : ((tok0 <= growA) ? 0x0000FFFFu : 0u);
                    const uint32_t mB = (tok0 + 1 <= growB) ? 0xFFFFFFFFu
                                       : ((tok0 <= growB) ? 0x0000FFFFu : 0u);
                    __half2 hA = __floats2half2_rn(sacc[j][0], sacc[j][1]);
                    __half2 hB = __floats2half2_rn(sacc[j][2], sacc[j][3]);
                    uint32_t pa = h2ex2(*(uint32_t*)&hA) & mA;
                    uint32_t pb = h2ex2(*(uint32_t*)&hB) & mB;
                    lA2 = __hadd2(lA2, *(__half2*)&pa);
                    lB2 = __hadd2(lB2, *(__half2*)&pb);
                    const int kt = j >> 1, hi = (j & 1) * 2;
                    pf[kt][hi]     = pa;
                    pf[kt][hi + 1] = pb;
                }
            }
            {
                float2 fA = __half22float2(lA2);
                float2 fB = __half22float2(lB2);
                lsumA += fA.x + fA.y;
                lsumB += fB.x + fB.y;
            }

#pragma unroll
            for (int kt = 0; kt < 4; kt++) {
                const int c = kt * 2 + csel;
                uint32_t vh[4][4];
#pragma unroll
                for (int jdp = 0; jdp < 4; jdp++) {
                    const int dim = jdp * 16 + rsel;
                    ldsm4(vh[jdp], vbase + dim * 128 + ((c ^ (dim & 7)) * 16));
                }
#pragma unroll
                for (int jdp = 0; jdp < 4; jdp++) {
                    mma16816(oacc[2 * jdp],     pf[kt], vh[jdp][0], vh[jdp][1]);
                    mma16816(oacc[2 * jdp + 1], pf[kt], vh[jdp][2], vh[jdp][3]);
                }
            }
        }
        __syncthreads();
    }

    lsumA += __shfl_xor_sync(FULL, lsumA, 1);
    lsumA += __shfl_xor_sync(FULL, lsumA, 2);
    lsumB += __shfl_xor_sync(FULL, lsumB, 1);
    lsumB += __shfl_xor_sync(FULL, lsumB, 2);

    // ---- store partials (fp16) + row sums ----
    const size_t pqbase = (((size_t)(b * NQT + qt) * MAXCH) * 128) * HS;
    const size_t pbase  = pqbase + (size_t)ch * 128 * HS;
    const int rowA = w * 16 + gid;
#pragma unroll
    for (int jd = 0; jd < 8; jd++) {
        const int col = jd * 8 + tig * 2;
        __half2 hA = __floats2half2_rn(oacc[jd][0], oacc[jd][1]);
        __half2 hB = __floats2half2_rn(oacc[jd][2], oacc[jd][3]);
        *(uint32_t*)(&g_part[pbase + (size_t)rowA * HS + col]) = *(uint32_t*)&hA;
        *(uint32_t*)(&g_part[pbase + (size_t)(rowA + 8) * HS + col]) = *(uint32_t*)&hB;
    }
    const size_t lqbase = ((size_t)(b * NQT + qt) * MAXCH) * 128;
    if (tig == 0) {
        g_l[lqbase + ch * 128 + rowA] = lsumA;
        g_l[lqbase + ch * 128 + rowA + 8] = lsumB;
    }

    // ---- split-K fixup: last chunk CTA merges (threadfence-reduction) ----
    __threadfence();
    __syncthreads();
    if (tid == 0) {
        const int old = atomicAdd(&g_cnt[b * NQT + qt], 1);
        s_last = (old == nch - 1);
    }
    __syncthreads();
    if (!s_last) return;
    __threadfence();   // acquire: other chunks' stores now visible

#pragma unroll 1
    for (int rg = 0; rg < 8; rg++) {
        const int row = rg * 16 + (tid >> 4);
        const int d0  = (tid & 15) * 4;
        float4 acc = make_float4(0.f, 0.f, 0.f, 0.f);
        float L = 0.f;
#pragma unroll 4
        for (int c = 0; c < nch; c++) {
            L += g_l[lqbase + c * 128 + row];
            const uint2 u = *(const uint2*)(&g_part[pqbase + ((size_t)c * 128 + row) * HS + d0]);
            const float2 v0 = __half22float2(*(const __half2*)&u.x);
            const float2 v1 = __half22float2(*(const __half2*)&u.y);
            acc.x += v0.x; acc.y += v0.y; acc.z += v1.x; acc.w += v1.y;
        }
        const float inv = 1.f / L;
        float* op = out + ((size_t)b * TSEQ + qt * 128 + row) * HS + d0;
        *(float4*)op = make_float4(acc.x * inv, acc.y * inv, acc.z * inv, acc.w * inv);
    }
    if (tid == 0) g_cnt[b * NQT + qt] = 0;   // self-reset for next graph replay
}

// ---------------------------------------------------------------------------
extern "C" void kernel_launch(void* const* d_in, const int* in_sizes, int n_in,
                              void* d_out, int out_size)
{
    const float* x  = (const float*)d_in[0];
    const float* Wq = (const float*)d_in[1];
    const float* Wk = (const float*)d_in[2];
    const float* Wv = (const float*)d_in[3];
    float* out = (float*)d_out;

    cudaFuncSetAttribute(attn_kernel, cudaFuncAttributeMaxDynamicSharedMemorySize, SMEM_TOTAL);
    cudaFuncSetAttribute(proj_kernel, cudaFuncAttributeMaxDynamicSharedMemorySize, PROJ_SMEM);

    wp_kernel<<<38, 256>>>(Wq, Wk, Wv);
    proj_kernel<<<128, 256, PROJ_SMEM>>>(x);
    attn_kernel<<<BATCH * ITEMS_PER_B, 256, SMEM_TOTAL>>>(out);
}

// round 17
// speedup vs baseline: 1.2189x; 1.2189x over previous
#include <cuda_runtime.h>
#include <cuda_fp16.h>
#include <cstdint>
#include <math.h>

#define BATCH 4
#define TSEQ  4096
#define EMB   100
#define HS    64
#define NQT   32            // 128-row q tiles per batch
#define MAXCH 4             // max chunks per qt (16-tile chunks)
#define ITEMS_PER_B 80      // sum over qt of ceil((2qt+2)/16)

// ---------------- global scratch ----------------
__device__ __align__(16) __half g_q[BATCH * TSEQ * HS];          // q * log2e/8, fp16
__device__ __align__(16) __half g_k[BATCH * TSEQ * HS];          // fp16
__device__ __align__(16) __half g_vt[BATCH * 64 * HS * 64];      // [ktile][dim][tok]
__device__ __align__(16) float g_wp[3 * 50 * HS * 2];            // W pairs: [m][e/2][j][2]
__device__ __align__(16) __half g_part[BATCH * NQT * MAXCH * 128 * HS]; // O partials fp16
__device__ float g_l[BATCH * NQT * MAXCH * 128];                 // row sums fp32

// ---------------- PTX helpers ---------------
__device__ __forceinline__ uint32_t smem_u32(const void* p) {
    uint32_t a;
    asm("{ .reg .u64 t; cvta.to.shared.u64 t, %1; cvt.u32.u64 %0, t; }" : "=r"(a) : "l"(p));
    return a;
}
__device__ __forceinline__ uint32_t h2ex2(uint32_t x) {
    uint32_t r; asm("ex2.approx.f16x2 %0, %1;" : "=r"(r) : "r"(x)); return r;
}
__device__ __forceinline__ void ffma2(unsigned long long& d,
                                      unsigned long long a, unsigned long long b) {
    asm("fma.rn.f32x2 %0, %1, %2, %0;" : "+l"(d) : "l"(a), "l"(b));
}
__device__ __forceinline__ void cpa16(uint32_t dst, const void* src) {
    asm volatile("cp.async.cg.shared.global [%0], [%1], 16;" :: "r"(dst), "l"(src));
}
__device__ __forceinline__ void cpa_commit() { asm volatile("cp.async.commit_group;" ::: "memory"); }
__device__ __forceinline__ void cpa_wait1()  { asm volatile("cp.async.wait_group 1;" ::: "memory"); }
__device__ __forceinline__ void ldsm4(uint32_t* r, uint32_t addr) {
    asm volatile("ldmatrix.sync.aligned.m8n8.x4.shared.b16 {%0,%1,%2,%3}, [%4];"
        : "=r"(r[0]), "=r"(r[1]), "=r"(r[2]), "=r"(r[3]) : "r"(addr));
}
__device__ __forceinline__ void mma16816(float* c, const uint32_t* a, uint32_t b0, uint32_t b1) {
    asm volatile("mma.sync.aligned.m16n8k16.row.col.f32.f16.f16.f32 "
        "{%0,%1,%2,%3}, {%4,%5,%6,%7}, {%8,%9}, {%0,%1,%2,%3};"
        : "+f"(c[0]), "+f"(c[1]), "+f"(c[2]), "+f"(c[3])
        : "r"(a[0]), "r"(a[1]), "r"(a[2]), "r"(a[3]), "r"(b0), "r"(b1));
}

// attn SMEM: K and V tile PAIRS, double buffered (16KB per pair per part)
#define OFF_K 0
#define OFF_V 32768
#define SMEM_TOTAL 65536

// proj SMEM
#define XS_PAD 102
#define PROJ_XS_FLOATS (128 * XS_PAD)
#define PROJ_WS_FLOATS (3 * 50 * HS * 2)
#define PROJ_SMEM ((PROJ_XS_FLOATS + PROJ_WS_FLOATS) * 4)

// ---------------------------------------------------------------------------
// Kernel 0: repack W -> g_wp[m][e/2][j][2]
// ---------------------------------------------------------------------------
__global__ void wp_kernel(const float* __restrict__ Wq,
                          const float* __restrict__ Wk,
                          const float* __restrict__ Wv)
{
    for (int i = blockIdx.x * 256 + threadIdx.x; i < 3 * 50 * HS; i += gridDim.x * 256) {
        const int m = i / (50 * HS);
        const int r = i % (50 * HS);
        const int ep = r / HS, j = r % HS;
        const float* W = (m == 0) ? Wq : ((m == 1) ? Wk : Wv);
        g_wp[i * 2 + 0] = W[(2 * ep)     * HS + j];
        g_wp[i * 2 + 1] = W[(2 * ep + 1) * HS + j];
    }
}

// ---------------------------------------------------------------------------
// Kernel 1: fused Q/K/V projection, SMEM-tiled, packed f32x2 FMA, m-fused.
// ---------------------------------------------------------------------------
__global__ __launch_bounds__(256) void proj_kernel(const float* __restrict__ x)
{
    extern __shared__ float psm[];
    float* xs = psm;                        // [128][XS_PAD]
    float* ws = psm + PROJ_XS_FLOATS;       // [3][50][64][2]

    const int tid = threadIdx.x;
    const int row0g = blockIdx.x * 128;

    const float* xg = x + (size_t)row0g * EMB;
    for (int i = tid; i < 128 * EMB; i += 256)
        xs[(i / EMB) * XS_PAD + (i % EMB)] = xg[i];
    for (int i = tid; i < PROJ_WS_FLOATS / 4; i += 256)
        *(float4*)(ws + i * 4) = *(const float4*)(g_wp + i * 4);
    __syncthreads();

    const int rt = tid >> 4;
    const int ct = tid & 15;
    const int row0 = rt * 8;
    const int j0 = ct * 4;

    unsigned long long acc[3][32];
#pragma unroll
    for (int m = 0; m < 3; m++)
#pragma unroll
        for (int q = 0; q < 32; q++) acc[m][q] = 0ull;

    const float* wsb = ws + j0 * 2;
#pragma unroll 1
    for (int ep = 0; ep < 50; ep++) {
        unsigned long long xv[8];
#pragma unroll
        for (int r = 0; r < 8; r++)
            xv[r] = *(const unsigned long long*)(&xs[(row0 + r) * XS_PAD + 2 * ep]);
#pragma unroll
        for (int m = 0; m < 3; m++) {
            const float* wsm = wsb + m * (50 * HS * 2) + ep * (HS * 2);
            const ulonglong2 wa = *(const ulonglong2*)(wsm);
            const ulonglong2 wb = *(const ulonglong2*)(wsm + 4);
#pragma unroll
            for (int r = 0; r < 8; r++) {
                ffma2(acc[m][r * 4 + 0], xv[r], wa.x);
                ffma2(acc[m][r * 4 + 1], xv[r], wa.y);
                ffma2(acc[m][r * 4 + 2], xv[r], wb.x);
                ffma2(acc[m][r * 4 + 3], xv[r], wb.y);
            }
        }
    }

    const float QSCALE = 0.125f * 1.4426950408889634f;

#pragma unroll
    for (int r = 0; r < 8; r++) {
        float v0 = ((float2*)&acc[0][r*4+0])->x + ((float2*)&acc[0][r*4+0])->y;
        float v1 = ((float2*)&acc[0][r*4+1])->x + ((float2*)&acc[0][r*4+1])->y;
        float v2 = ((float2*)&acc[0][r*4+2])->x + ((float2*)&acc[0][r*4+2])->y;
        float v3 = ((float2*)&acc[0][r*4+3])->x + ((float2*)&acc[0][r*4+3])->y;
        __half2 h01 = __floats2half2_rn(v0 * QSCALE, v1 * QSCALE);
        __half2 h23 = __floats2half2_rn(v2 * QSCALE, v3 * QSCALE);
        uint2 u = make_uint2(*(uint32_t*)&h01, *(uint32_t*)&h23);
        *(uint2*)(&g_q[(size_t)(row0g + row0 + r) * HS + j0]) = u;
    }
#pragma unroll
    for (int r = 0; r < 8; r++) {
        float v0 = ((float2*)&acc[1][r*4+0])->x + ((float2*)&acc[1][r*4+0])->y;
        float v1 = ((float2*)&acc[1][r*4+1])->x + ((float2*)&acc[1][r*4+1])->y;
        float v2 = ((float2*)&acc[1][r*4+2])->x + ((float2*)&acc[1][r*4+2])->y;
        float v3 = ((float2*)&acc[1][r*4+3])->x + ((float2*)&acc[1][r*4+3])->y;
        __half2 h01 = __floats2half2_rn(v0, v1);
        __half2 h23 = __floats2half2_rn(v2, v3);
        uint2 u = make_uint2(*(uint32_t*)&h01, *(uint32_t*)&h23);
        *(uint2*)(&g_k[(size_t)(row0g + row0 + r) * HS + j0]) = u;
    }
    {
        const int grow0 = row0g + row0;
        const int kt = grow0 >> 6;
        const int tok0 = grow0 & 63;
#pragma unroll
        for (int jj = 0; jj < 4; jj++) {
            union { __half h[8]; uint4 u; } vt;
#pragma unroll
            for (int r = 0; r < 8; r++) {
                const float2 f = *(float2*)&acc[2][r * 4 + jj];
                vt.h[r] = __float2half_rn(f.x + f.y);
            }
            *(uint4*)(&g_vt[(size_t)kt * (HS * 64) + (j0 + jj) * 64 + tok0]) = vt.u;
        }
    }
}

// ---------------------------------------------------------------------------
// Kernel 2: mma.sync fp16 split-K causal flash attention.
// 16-tile chunks (8 pipeline pairs) -> 320 CTAs = 1.08 waves at 2 CTA/SM.
// ---------------------------------------------------------------------------
__device__ __forceinline__ void issue_pair(uint32_t sb, int tid, int buf,
                                           int b, int ktile)
{
    const char* kp = (const char*)g_k + (size_t)(b * TSEQ + ktile * 64) * HS * 2;
    const char* vp = (const char*)g_vt + (size_t)(b * 64 + ktile) * (HS * 64) * 2;
#pragma unroll
    for (int rep = 0; rep < 4; rep++) {
        const int idx = tid + rep * 256;
        const int row = idx >> 3, c = idx & 7;
        const int dsw = row * 128 + ((c ^ (row & 7)) * 16);
        const int ssw = row * 128 + c * 16;
        cpa16(sb + OFF_K + buf * 16384 + dsw, kp + ssw);
        cpa16(sb + OFF_V + buf * 16384 + dsw, vp + ssw);
    }
}

__global__ __launch_bounds__(256, 2) void attn_kernel()
{
    extern __shared__ char sm[];
    const uint32_t sb = smem_u32(sm);
    const int tid  = threadIdx.x;
    const int w    = tid >> 5;
    const int lane = tid & 31;
    const int gid  = lane >> 2;
    const int tig  = lane & 3;
    const unsigned FULL = 0xffffffffu;

    // ---- decode blockIdx -> (b, qt, ch); heavy items first ----
    // qt groups of 8 share nch = g = qt/8 + 1; cumulative items before
    // group g is 4g(g-1); per batch total = 80.
    const int b = blockIdx.x & 3;
    const int i = 79 - (int)(blockIdx.x >> 2);
    int g = 1;
    while (i >= 4 * g * (g + 1)) g++;
    const int off = i - 4 * g * (g - 1);
    const int qt = 8 * (g - 1) + off / g;
    const int ch = off % g;
    const int k0t = ch * 16;                       // first 64-token k-tile
    const int n = min(k0t + 16, 2 * qt + 2) - k0t; // even, >=2
    const int np = n >> 1;

    uint32_t qf[4][4];
    {
        const __half* qb = g_q + (size_t)(b * TSEQ + qt * 128 + w * 16) * HS;
#pragma unroll
        for (int kk = 0; kk < 4; kk++) {
            const int cA = kk * 16 + tig * 2;
            qf[kk][0] = *(const uint32_t*)(qb + gid * HS + cA);
            qf[kk][1] = *(const uint32_t*)(qb + (gid + 8) * HS + cA);
            qf[kk][2] = *(const uint32_t*)(qb + gid * HS + cA + 8);
            qf[kk][3] = *(const uint32_t*)(qb + (gid + 8) * HS + cA + 8);
        }
    }

    float oacc[8][4];
#pragma unroll
    for (int j = 0; j < 8; j++)
#pragma unroll
        for (int q = 0; q < 4; q++) oacc[j][q] = 0.f;
    float lsumA = 0.f, lsumB = 0.f;
    const int growA = qt * 128 + w * 16 + gid;
    const int growB = growA + 8;
    const int wrow0 = qt * 128 + w * 16;

    const int lgrp = lane >> 3, li = lane & 7;
    const int rsel = (lgrp >> 1) * 8 + li;
    const int csel = lgrp & 1;

    issue_pair(sb, tid, 0, b, k0t);
    cpa_commit();

    for (int pt = 0; pt < np; pt++) {
        const int buf = pt & 1;
        if (pt + 1 < np) issue_pair(sb, tid, buf ^ 1, b, k0t + 2 * (pt + 1));
        cpa_commit();
        cpa_wait1();
        __syncthreads();

#pragma unroll
        for (int sub = 0; sub < 2; sub++) {
            const int tglob = k0t + 2 * pt + sub;
            const uint32_t kbase = sb + OFF_K + buf * 16384 + sub * 8192;
            const uint32_t vbase = sb + OFF_V + buf * 16384 + sub * 8192;

            float sacc[8][4];
#pragma unroll
            for (int j = 0; j < 8; j++)
#pragma unroll
                for (int q = 0; q < 4; q++) sacc[j][q] = 0.f;

#pragma unroll
            for (int kk = 0; kk < 4; kk++) {
                const int c = kk * 2 + csel;
                uint32_t bh[4][4];
#pragma unroll
                for (int jp = 0; jp < 4; jp++) {
                    const int tok = jp * 16 + rsel;
                    ldsm4(bh[jp], kbase + tok * 128 + ((c ^ (tok & 7)) * 16));
                }
#pragma unroll
                for (int jp = 0; jp < 4; jp++) {
                    mma16816(sacc[2 * jp],     qf[kk], bh[jp][0], bh[jp][1]);
                    mma16816(sacc[2 * jp + 1], qf[kk], bh[jp][2], bh[jp][3]);
                }
            }

            uint32_t pf[4][4];
            __half2 lA2 = __floats2half2_rn(0.f, 0.f);
            __half2 lB2 = lA2;
            const bool full = (tglob * 64 + 63) <= wrow0;
            if (full) {
#pragma unroll
                for (int j = 0; j < 8; j++) {
                    __half2 hA = __floats2half2_rn(sacc[j][0], sacc[j][1]);
                    __half2 hB = __floats2half2_rn(sacc[j][2], sacc[j][3]);
                    uint32_t pa = h2ex2(*(uint32_t*)&hA);
                    uint32_t pb = h2ex2(*(uint32_t*)&hB);
                    lA2 = __hadd2(lA2, *(__half2*)&pa);
                    lB2 = __hadd2(lB2, *(__half2*)&pb);
                    const int kt = j >> 1, hi = (j & 1) * 2;
                    pf[kt][hi]     = pa;
                    pf[kt][hi + 1] = pb;
                }
            } else {
#pragma unroll
                for (int j = 0; j < 8; j++) {
                    const int tok0 = tglob * 64 + j * 8 + tig * 2;
                    const uint32_t mA = (tok0 + 1 <= growA) ? 0xFFFFFFFFu
                                       : ((tok0 <= growA) ? 0x0000FFFFu : 0u);
                    const uint32_t mB = (tok0 + 1 <= growB) ? 0xFFFFFFFFu
                                       : ((tok0 <= growB) ? 0x0000FFFFu : 0u);
                    __half2 hA = __floats2half2_rn(sacc[j][0], sacc[j][1]);
                    __half2 hB = __floats2half2_rn(sacc[j][2], sacc[j][3]);
                    uint32_t pa = h2ex2(*(uint32_t*)&hA) & mA;
                    uint32_t pb = h2ex2(*(uint32_t*)&hB) & mB;
                    lA2 = __hadd2(lA2, *(__half2*)&pa);
                    lB2 = __hadd2(lB2, *(__half2*)&pb);
                    const int kt = j >> 1, hi = (j & 1) * 2;
                    pf[kt][hi]     = pa;
                    pf[kt][hi + 1] = pb;
                }
            }
            {
                float2 fA = __half22float2(lA2);
                float2 fB = __half22float2(lB2);
                lsumA += fA.x + fA.y;
                lsumB += fB.x + fB.y;
            }

#pragma unroll
            for (int kt = 0; kt < 4; kt++) {
                const int c = kt * 2 + csel;
                uint32_t vh[4][4];
#pragma unroll
                for (int jdp = 0; jdp < 4; jdp++) {
                    const int dim = jdp * 16 + rsel;
                    ldsm4(vh[jdp], vbase + dim * 128 + ((c ^ (dim & 7)) * 16));
                }
#pragma unroll
                for (int jdp = 0; jdp < 4; jdp++) {
                    mma16816(oacc[2 * jdp],     pf[kt], vh[jdp][0], vh[jdp][1]);
                    mma16816(oacc[2 * jdp + 1], pf[kt], vh[jdp][2], vh[jdp][3]);
                }
            }
        }
        __syncthreads();
    }

    lsumA += __shfl_xor_sync(FULL, lsumA, 1);
    lsumA += __shfl_xor_sync(FULL, lsumA, 2);
    lsumB += __shfl_xor_sync(FULL, lsumB, 1);
    lsumB += __shfl_xor_sync(FULL, lsumB, 2);

    const size_t pbase = (((size_t)(b * NQT + qt) * MAXCH + ch) * 128) * HS;
    const int rowA = w * 16 + gid;
#pragma unroll
    for (int jd = 0; jd < 8; jd++) {
        const int col = jd * 8 + tig * 2;
        __half2 hA = __floats2half2_rn(oacc[jd][0], oacc[jd][1]);
        __half2 hB = __floats2half2_rn(oacc[jd][2], oacc[jd][3]);
        *(uint32_t*)(&g_part[pbase + (size_t)rowA * HS + col]) = *(uint32_t*)&hA;
        *(uint32_t*)(&g_part[pbase + (size_t)(rowA + 8) * HS + col]) = *(uint32_t*)&hB;
    }
    if (tig == 0) {
        const size_t lbase = (((size_t)(b * NQT + qt) * MAXCH + ch) * 128);
        g_l[lbase + rowA] = lsumA;
        g_l[lbase + rowA + 8] = lsumB;
    }
}

// ---------------------------------------------------------------------------
// Kernel 3: merge split-K partials (fp16 partials, fp32 sums; nch <= 4)
// ---------------------------------------------------------------------------
__global__ __launch_bounds__(256) void merge_kernel(float* __restrict__ out)
{
    const int bid = blockIdx.x;
    const int rg  = bid & 7;
    const int qt  = (bid >> 3) & 31;
    const int b   = bid >> 8;
    const int nch = qt / 8 + 1;
    const int tid = threadIdx.x;
    const int row = rg * 16 + (tid >> 4);
    const int d0  = (tid & 15) * 4;

    const size_t base = (size_t)(b * NQT + qt) * MAXCH * 128;
    float4 acc = make_float4(0.f, 0.f, 0.f, 0.f);
    float L = 0.f;
#pragma unroll 4
    for (int c = 0; c < nch; c++) {
        L += g_l[base + c * 128 + row];
        const uint2 u = *(const uint2*)(&g_part[(base + c * 128 + row) * HS + d0]);
        const float2 v0 = __half22float2(*(const __half2*)&u.x);
        const float2 v1 = __half22float2(*(const __half2*)&u.y);
        acc.x += v0.x; acc.y += v0.y; acc.z += v1.x; acc.w += v1.y;
    }
    const float inv = 1.f / L;
    float* op = out + ((size_t)b * TSEQ + qt * 128 + row) * HS + d0;
    *(float4*)op = make_float4(acc.x * inv, acc.y * inv, acc.z * inv, acc.w * inv);
}

// ---------------------------------------------------------------------------
extern "C" void kernel_launch(void* const* d_in, const int* in_sizes, int n_in,
                              void* d_out, int out_size)
{
    const float* x  = (const float*)d_in[0];
    const float* Wq = (const float*)d_in[1];
    const float* Wk = (const float*)d_in[2];
    const float* Wv = (const float*)d_in[3];
    float* out = (float*)d_out;

    cudaFuncSetAttribute(attn_kernel, cudaFuncAttributeMaxDynamicSharedMemorySize, SMEM_TOTAL);
    cudaFuncSetAttribute(proj_kernel, cudaFuncAttributeMaxDynamicSharedMemorySize, PROJ_SMEM);

    wp_kernel<<<38, 256>>>(Wq, Wk, Wv);
    proj_kernel<<<128, 256, PROJ_SMEM>>>(x);
    attn_kernel<<<BATCH * ITEMS_PER_B, 256, SMEM_TOTAL>>>();
    merge_kernel<<<BATCH * NQT * 8, 256>>>(out);
}